// round 2
// baseline (speedup 1.0000x reference)
#include <cuda_runtime.h>
#include <math.h>

// Shapes (fixed by the problem)
#define BATCH 2
#define SEQ   2048
#define DM    1024
#define HEADS 16
#define DK    64
#define MROWS (BATCH * SEQ)          // 4096

// Scratch: device globals (allocation-free rule)
__device__ float g_Q[BATCH * HEADS * SEQ * DK];     // [b,h,s,d]
__device__ float g_K[BATCH * HEADS * SEQ * DK];
__device__ float g_V[BATCH * HEADS * SEQ * DK];
__device__ float g_ATT[MROWS * DM];                 // [b,s, h*64+d]

// ---------------------------------------------------------------------------
// GEMM: C = A[M,1024] @ W[1024,1024] + bias, 128x128x16 tile, 256 threads,
// 8x8 per-thread. Writes split-head QKV scratch (z selects Q/K/V).
// ---------------------------------------------------------------------------
__global__ __launch_bounds__(256) void mha_gemm_qkv(
    const float* __restrict__ A,
    const float* __restrict__ Wq, const float* __restrict__ Wk, const float* __restrict__ Wv,
    const float* __restrict__ bq, const float* __restrict__ bk, const float* __restrict__ bv)
{
    __shared__ float As[16][128];
    __shared__ float Bs[16][128];

    const int z = blockIdx.z;
    const float* W    = (z == 0) ? Wq : (z == 1) ? Wk : Wv;
    const float* bias = (z == 0) ? bq : (z == 1) ? bk : bv;
    float* O          = (z == 0) ? g_Q : (z == 1) ? g_K : g_V;

    const int tid = threadIdx.x;
    const int tx = tid & 15;            // 0..15 (cols)
    const int ty = tid >> 4;            // 0..15 (rows)
    const int bm = blockIdx.y * 128;
    const int bn = blockIdx.x * 128;

    float acc[8][8] = {};

    for (int k0 = 0; k0 < DM; k0 += 16) {
        // A tile: 128 rows x 16 k (transposed into As[k][m])
        #pragma unroll
        for (int i = 0; i < 2; i++) {
            int idx = tid + i * 256;          // 0..511 float4 slots
            int row = idx >> 2;               // 0..127
            int k4  = (idx & 3) * 4;
            float4 v = *(const float4*)&A[(size_t)(bm + row) * DM + k0 + k4];
            As[k4 + 0][row] = v.x;
            As[k4 + 1][row] = v.y;
            As[k4 + 2][row] = v.z;
            As[k4 + 3][row] = v.w;
        }
        // W tile: 16 k x 128 n
        #pragma unroll
        for (int i = 0; i < 2; i++) {
            int idx = tid + i * 256;
            int kr  = idx >> 5;               // 0..15
            int n4  = (idx & 31) * 4;
            *(float4*)&Bs[kr][n4] = *(const float4*)&W[(size_t)(k0 + kr) * DM + bn + n4];
        }
        __syncthreads();

        #pragma unroll
        for (int kk = 0; kk < 16; kk++) {
            float a[8], b[8];
            *(float4*)&a[0] = *(const float4*)&As[kk][ty * 8];
            *(float4*)&a[4] = *(const float4*)&As[kk][ty * 8 + 4];
            *(float4*)&b[0] = *(const float4*)&Bs[kk][tx * 8];
            *(float4*)&b[4] = *(const float4*)&Bs[kk][tx * 8 + 4];
            #pragma unroll
            for (int i = 0; i < 8; i++)
                #pragma unroll
                for (int j = 0; j < 8; j++)
                    acc[i][j] += a[i] * b[j];
        }
        __syncthreads();
    }

    // Epilogue: bias + split-head store [b,h,s,d]
    #pragma unroll
    for (int i = 0; i < 8; i++) {
        int m = bm + ty * 8 + i;
        int b = m >> 11;                  // /2048
        int s = m & 2047;
        #pragma unroll
        for (int j4 = 0; j4 < 8; j4 += 4) {
            int col = bn + tx * 8 + j4;
            int h = col >> 6;
            int d = col & 63;
            float4 v;
            v.x = acc[i][j4 + 0] + bias[col + 0];
            v.y = acc[i][j4 + 1] + bias[col + 1];
            v.z = acc[i][j4 + 2] + bias[col + 2];
            v.w = acc[i][j4 + 3] + bias[col + 3];
            size_t dst = ((size_t)(b * HEADS + h) * SEQ + s) * DK + d;
            *(float4*)&O[dst] = v;
        }
    }
}

// Output projection: reads g_ATT directly (no symbol-address call on host).
__global__ __launch_bounds__(256) void mha_gemm_out(
    const float* __restrict__ W,
    const float* __restrict__ bias, float* __restrict__ C)
{
    __shared__ float As[16][128];
    __shared__ float Bs[16][128];

    const float* A = g_ATT;

    const int tid = threadIdx.x;
    const int tx = tid & 15;
    const int ty = tid >> 4;
    const int bm = blockIdx.y * 128;
    const int bn = blockIdx.x * 128;

    float acc[8][8] = {};

    for (int k0 = 0; k0 < DM; k0 += 16) {
        #pragma unroll
        for (int i = 0; i < 2; i++) {
            int idx = tid + i * 256;
            int row = idx >> 2;
            int k4  = (idx & 3) * 4;
            float4 v = *(const float4*)&A[(size_t)(bm + row) * DM + k0 + k4];
            As[k4 + 0][row] = v.x;
            As[k4 + 1][row] = v.y;
            As[k4 + 2][row] = v.z;
            As[k4 + 3][row] = v.w;
        }
        #pragma unroll
        for (int i = 0; i < 2; i++) {
            int idx = tid + i * 256;
            int kr  = idx >> 5;
            int n4  = (idx & 31) * 4;
            *(float4*)&Bs[kr][n4] = *(const float4*)&W[(size_t)(k0 + kr) * DM + bn + n4];
        }
        __syncthreads();

        #pragma unroll
        for (int kk = 0; kk < 16; kk++) {
            float a[8], b[8];
            *(float4*)&a[0] = *(const float4*)&As[kk][ty * 8];
            *(float4*)&a[4] = *(const float4*)&As[kk][ty * 8 + 4];
            *(float4*)&b[0] = *(const float4*)&Bs[kk][tx * 8];
            *(float4*)&b[4] = *(const float4*)&Bs[kk][tx * 8 + 4];
            #pragma unroll
            for (int i = 0; i < 8; i++)
                #pragma unroll
                for (int j = 0; j < 8; j++)
                    acc[i][j] += a[i] * b[j];
        }
        __syncthreads();
    }

    #pragma unroll
    for (int i = 0; i < 8; i++) {
        int m = bm + ty * 8 + i;
        #pragma unroll
        for (int j4 = 0; j4 < 8; j4 += 4) {
            int col = bn + tx * 8 + j4;
            float4 v;
            v.x = acc[i][j4 + 0] + bias[col + 0];
            v.y = acc[i][j4 + 1] + bias[col + 1];
            v.z = acc[i][j4 + 2] + bias[col + 2];
            v.w = acc[i][j4 + 3] + bias[col + 3];
            *(float4*)&C[(size_t)m * DM + col] = v;
        }
    }
}

// ---------------------------------------------------------------------------
// Flash attention: one block = 128 queries of one (b,h). Online softmax,
// q & o fully in registers, K/V 64x64 fp32 tiles in smem.
// ---------------------------------------------------------------------------
__global__ __launch_bounds__(128, 1) void mha_flash()
{
    __shared__ float Ks[64][64];
    __shared__ float Vs[64][64];

    const int bh   = blockIdx.x >> 4;          // 0..31 (b*16+h)
    const int qblk = blockIdx.x & 15;
    const int tid  = threadIdx.x;
    const int qidx = qblk * 128 + tid;         // 0..2047

    const float* qptr = &g_Q[((size_t)bh * SEQ + qidx) * DK];
    const float* Kb   = &g_K[(size_t)bh * SEQ * DK];
    const float* Vb   = &g_V[(size_t)bh * SEQ * DK];

    float q[DK], o[DK];
    #pragma unroll
    for (int d4 = 0; d4 < DK; d4 += 4) {
        float4 v = *(const float4*)&qptr[d4];
        q[d4 + 0] = v.x; q[d4 + 1] = v.y; q[d4 + 2] = v.z; q[d4 + 3] = v.w;
        o[d4 + 0] = 0.f; o[d4 + 1] = 0.f; o[d4 + 2] = 0.f; o[d4 + 3] = 0.f;
    }

    float mrun = -INFINITY;
    float lrun = 0.f;
    const float scale = 0.125f;                // 1/sqrt(64)

    for (int t = 0; t < SEQ / 64; t++) {
        __syncthreads();
        // Load K/V tile: 4096 floats each = 1024 float4, 128 threads -> 8 each
        const float4* Ksrc = (const float4*)(Kb + (size_t)t * 64 * DK);
        const float4* Vsrc = (const float4*)(Vb + (size_t)t * 64 * DK);
        #pragma unroll
        for (int i = 0; i < 8; i++) {
            int idx = tid + i * 128;
            ((float4*)Ks)[idx] = Ksrc[idx];
            ((float4*)Vs)[idx] = Vsrc[idx];
        }
        __syncthreads();

        #pragma unroll 2
        for (int j = 0; j < 64; j++) {
            float s = 0.f;
            #pragma unroll
            for (int d4 = 0; d4 < DK; d4 += 4) {
                float4 kv = *(const float4*)&Ks[j][d4];
                s += q[d4 + 0] * kv.x + q[d4 + 1] * kv.y
                   + q[d4 + 2] * kv.z + q[d4 + 3] * kv.w;
            }
            s *= scale;
            if (s > mrun) {
                float corr = __expf(mrun - s);     // exp(-inf)=0 on first hit
                mrun = s;
                lrun *= corr;
                #pragma unroll
                for (int d = 0; d < DK; d++) o[d] *= corr;
            }
            float p = __expf(s - mrun);
            lrun += p;
            #pragma unroll
            for (int d4 = 0; d4 < DK; d4 += 4) {
                float4 vv = *(const float4*)&Vs[j][d4];
                o[d4 + 0] += p * vv.x;
                o[d4 + 1] += p * vv.y;
                o[d4 + 2] += p * vv.z;
                o[d4 + 3] += p * vv.w;
            }
        }
    }

    const float inv = 1.0f / lrun;
    const int b = bh >> 4;
    const int h = bh & 15;
    float* optr = &g_ATT[((size_t)b * SEQ + qidx) * DM + h * DK];
    #pragma unroll
    for (int d4 = 0; d4 < DK; d4 += 4) {
        float4 v;
        v.x = o[d4 + 0] * inv;
        v.y = o[d4 + 1] * inv;
        v.z = o[d4 + 2] * inv;
        v.w = o[d4 + 3] * inv;
        *(float4*)&optr[d4] = v;
    }
}

// ---------------------------------------------------------------------------
extern "C" void kernel_launch(void* const* d_in, const int* in_sizes, int n_in,
                              void* d_out, int out_size)
{
    const float* x  = (const float*)d_in[0];
    const float* Wq = (const float*)d_in[1];
    const float* bq = (const float*)d_in[2];
    const float* Wk = (const float*)d_in[3];
    const float* bk = (const float*)d_in[4];
    const float* Wv = (const float*)d_in[5];
    const float* bv = (const float*)d_in[6];
    const float* Wo = (const float*)d_in[7];
    const float* bo = (const float*)d_in[8];
    float* out = (float*)d_out;

    // 1) QKV projections (z selects weight) -> split-head scratch
    dim3 gq(DM / 128, MROWS / 128, 3);
    mha_gemm_qkv<<<gq, 256>>>(x, Wq, Wk, Wv, bq, bk, bv);

    // 2) Flash attention -> g_ATT [b,s,h*64+d]
    mha_flash<<<BATCH * HEADS * (SEQ / 128), 128>>>();

    // 3) Output projection (reads g_ATT device global directly)
    dim3 go(DM / 128, MROWS / 128, 1);
    mha_gemm_out<<<go, 256>>>(Wo, bo, out);
}

// round 6
// speedup vs baseline: 1.3697x; 1.3697x over previous
#include <cuda_runtime.h>
#include <math.h>
#include <stdint.h>

// Shapes (fixed by the problem)
#define BATCH 2
#define SEQ   2048
#define DM    1024
#define HEADS 16
#define DK    64
#define MROWS (BATCH * SEQ)          // 4096

// Scratch: device globals (allocation-free rule)
__device__ float g_Q[BATCH * HEADS * SEQ * DK];     // [b,h,s,d]
__device__ float g_K[BATCH * HEADS * SEQ * DK];
__device__ float g_V[BATCH * HEADS * SEQ * DK];
__device__ float g_ATT[MROWS * DM];                 // [b,s, h*64+d]

// ---------------------------------------------------------------------------
// mma.sync tf32 GEMM (sm_80+ baseline ISA; tcgen05 unavailable at sm_103)
// C[4096,1024] = A @ W + bias.
// CTA tile 128x128, 256 threads = 8 warps in 2(m) x 4(n); warp tile 64x32.
// mma m16n8k8, K-chunk 32 (4 k-steps), double-buffered smem + reg prefetch.
// ---------------------------------------------------------------------------
#define A_STRIDE 36     // floats per m-row (128 rows)  -> frag loads conflict-free
#define B_STRIDE 136    // floats per k-row (32 rows)   -> frag loads conflict-free
#define A_FLOATS (128 * A_STRIDE)          // 4608
#define B_FLOATS (32 * B_STRIDE)           // 4352
#define BUF_FLOATS (A_FLOATS + B_FLOATS)   // 8960
#define OFF_BIAS 0
#define OFF_A    128
#define GEMM_SMEM ((128 + 2 * BUF_FLOATS) * 4)   // 72192 bytes

__device__ __forceinline__ float to_tf32(float x) {
    float y;
    asm("cvt.rna.tf32.f32 %0, %1;" : "=f"(y) : "f"(x));
    return y;
}

__device__ __forceinline__ void mma_tf32(float* c, const uint32_t* a, const uint32_t* b) {
    asm volatile(
        "mma.sync.aligned.m16n8k8.row.col.f32.tf32.tf32.f32 "
        "{%0,%1,%2,%3}, {%4,%5,%6,%7}, {%8,%9}, {%0,%1,%2,%3};"
        : "+f"(c[0]), "+f"(c[1]), "+f"(c[2]), "+f"(c[3])
        : "r"(a[0]), "r"(a[1]), "r"(a[2]), "r"(a[3]), "r"(b[0]), "r"(b[1]));
}

// isOut=0: z selects Wq/Wk/Wv and writes split-head g_Q/g_K/g_V.
// isOut=1: A := g_ATT, writes plain Cout.
__global__ __launch_bounds__(256, 1) void gemm_mma(
    const float* __restrict__ Ain,
    const float* __restrict__ W0, const float* __restrict__ W1, const float* __restrict__ W2,
    const float* __restrict__ b0, const float* __restrict__ b1, const float* __restrict__ b2,
    float* __restrict__ Cout, int isOut)
{
    extern __shared__ float smem[];

    const int z = blockIdx.z;
    const float* A    = isOut ? g_ATT : Ain;
    const float* W    = isOut ? W0 : (z == 0) ? W0 : (z == 1) ? W1 : W2;
    const float* bias = isOut ? b0 : (z == 0) ? b0 : (z == 1) ? b1 : b2;

    const int tid  = threadIdx.x;
    const int wid  = tid >> 5;
    const int lane = tid & 31;
    const int wm   = wid >> 2;          // 0..1
    const int wn   = wid & 3;           // 0..3
    const int g    = lane >> 2;         // 0..7
    const int tig  = lane & 3;          // 0..3

    const int bm = blockIdx.y * 128;
    const int bn = blockIdx.x * 128;

    if (tid < 128) smem[OFF_BIAS + tid] = bias[bn + tid];

    // Copy-index precompute
    const int a_row = tid >> 3;             // 0..31 (plus +32*j)
    const int a_kf  = tid & 7;              // float4 within 32-k row
    const int b_n4  = tid & 31;             // float4 within 128-n row
    // A: 1024 float4 slots, 4 per thread (rows tid>>3 + 32*j)
    // B: 1024 float4 slots, 4 per thread (k-rows tid>>5 + 8*j)

    float4 pa[4], pb[4];

    // ---- prologue: load + store chunk 0
    #pragma unroll
    for (int j = 0; j < 4; j++) {
        pa[j] = *(const float4*)&A[(size_t)(bm + a_row + j * 32) * DM + a_kf * 4];
        pb[j] = *(const float4*)&W[(size_t)((tid >> 5) + j * 8) * DM + bn + b_n4 * 4];
    }
    {
        float* As = smem + OFF_A;
        float* Bs = As + A_FLOATS;
        #pragma unroll
        for (int j = 0; j < 4; j++) {
            float* pA = &As[(a_row + j * 32) * A_STRIDE + a_kf * 4];
            pA[0] = to_tf32(pa[j].x); pA[1] = to_tf32(pa[j].y);
            pA[2] = to_tf32(pa[j].z); pA[3] = to_tf32(pa[j].w);
            float* pB = &Bs[((tid >> 5) + j * 8) * B_STRIDE + b_n4 * 4];
            pB[0] = to_tf32(pb[j].x); pB[1] = to_tf32(pb[j].y);
            pB[2] = to_tf32(pb[j].z); pB[3] = to_tf32(pb[j].w);
        }
    }
    __syncthreads();

    float c[4][4][4] = {};   // [mf][nf][4]

    for (int i = 0; i < 32; i++) {
        // prefetch next chunk into registers
        if (i < 31) {
            const int k0 = (i + 1) * 32;
            #pragma unroll
            for (int j = 0; j < 4; j++) {
                pa[j] = *(const float4*)&A[(size_t)(bm + a_row + j * 32) * DM + k0 + a_kf * 4];
                pb[j] = *(const float4*)&W[(size_t)(k0 + (tid >> 5) + j * 8) * DM + bn + b_n4 * 4];
            }
        }

        // compute on buffer i&1
        const float* As = smem + OFF_A + (i & 1) * BUF_FLOATS;
        const float* Bs = As + A_FLOATS;
        #pragma unroll
        for (int q = 0; q < 4; q++) {
            uint32_t af[4][4], bf[4][2];
            #pragma unroll
            for (int mf = 0; mf < 4; mf++) {
                const uint32_t* base = (const uint32_t*)&As[(wm * 64 + mf * 16 + g) * A_STRIDE + q * 8 + tig];
                af[mf][0] = base[0];
                af[mf][1] = base[8 * A_STRIDE];
                af[mf][2] = base[4];
                af[mf][3] = base[8 * A_STRIDE + 4];
            }
            #pragma unroll
            for (int nf = 0; nf < 4; nf++) {
                const uint32_t* base = (const uint32_t*)&Bs[(q * 8 + tig) * B_STRIDE + wn * 32 + nf * 8 + g];
                bf[nf][0] = base[0];
                bf[nf][1] = base[4 * B_STRIDE];
            }
            #pragma unroll
            for (int mf = 0; mf < 4; mf++)
                #pragma unroll
                for (int nf = 0; nf < 4; nf++)
                    mma_tf32(c[mf][nf], af[mf], bf[nf]);
        }

        // store prefetched chunk into other buffer
        if (i < 31) {
            float* Asn = smem + OFF_A + ((i + 1) & 1) * BUF_FLOATS;
            float* Bsn = Asn + A_FLOATS;
            #pragma unroll
            for (int j = 0; j < 4; j++) {
                float* pA = &Asn[(a_row + j * 32) * A_STRIDE + a_kf * 4];
                pA[0] = to_tf32(pa[j].x); pA[1] = to_tf32(pa[j].y);
                pA[2] = to_tf32(pa[j].z); pA[3] = to_tf32(pa[j].w);
                float* pB = &Bsn[((tid >> 5) + j * 8) * B_STRIDE + b_n4 * 4];
                pB[0] = to_tf32(pb[j].x); pB[1] = to_tf32(pb[j].y);
                pB[2] = to_tf32(pb[j].z); pB[3] = to_tf32(pb[j].w);
            }
            __syncthreads();
        }
    }

    // ---- epilogue: bias + store (split-head for QKV, plain for out-proj)
    float* O = isOut ? Cout : (z == 0) ? g_Q : (z == 1) ? g_K : g_V;

    #pragma unroll
    for (int mf = 0; mf < 4; mf++) {
        const int row = bm + wm * 64 + mf * 16 + g;
        #pragma unroll
        for (int nf = 0; nf < 4; nf++) {
            const int colt = wn * 32 + nf * 8 + tig * 2;      // col within 128-tile
            const float bx = smem[OFF_BIAS + colt];
            const float by = smem[OFF_BIAS + colt + 1];
            size_t base0, base1;
            if (isOut) {
                base0 = (size_t)row * DM + bn + colt;
                base1 = (size_t)(row + 8) * DM + bn + colt;
            } else {
                const int col = bn + colt;
                const int h = col >> 6, d0 = col & 63;
                const int b_ = row >> 11;
                const int s0 = row & 2047;
                base0 = ((size_t)(b_ * HEADS + h) * SEQ + s0) * DK + d0;
                base1 = base0 + 8 * DK;   // row+8 (same b,h since rows within 64-tile)
            }
            float2 v0 = { c[mf][nf][0] + bx, c[mf][nf][1] + by };
            float2 v1 = { c[mf][nf][2] + bx, c[mf][nf][3] + by };
            *(float2*)&O[base0] = v0;
            *(float2*)&O[base1] = v1;
        }
    }
}

// ---------------------------------------------------------------------------
// Flash attention (SIMT fp32): one block = 128 queries of one (b,h).
// ---------------------------------------------------------------------------
__global__ __launch_bounds__(128, 1) void mha_flash()
{
    __shared__ float Ks[64][64];
    __shared__ float Vs[64][64];

    const int bh   = blockIdx.x >> 4;          // 0..31 (b*16+h)
    const int qblk = blockIdx.x & 15;
    const int tid  = threadIdx.x;
    const int qidx = qblk * 128 + tid;         // 0..2047

    const float* qptr = &g_Q[((size_t)bh * SEQ + qidx) * DK];
    const float* Kb   = &g_K[(size_t)bh * SEQ * DK];
    const float* Vb   = &g_V[(size_t)bh * SEQ * DK];

    float q[DK], o[DK];
    #pragma unroll
    for (int d4 = 0; d4 < DK; d4 += 4) {
        float4 v = *(const float4*)&qptr[d4];
        q[d4 + 0] = v.x; q[d4 + 1] = v.y; q[d4 + 2] = v.z; q[d4 + 3] = v.w;
        o[d4 + 0] = 0.f; o[d4 + 1] = 0.f; o[d4 + 2] = 0.f; o[d4 + 3] = 0.f;
    }

    float mrun = -INFINITY;
    float lrun = 0.f;
    const float scale = 0.125f;                // 1/sqrt(64)

    for (int t = 0; t < SEQ / 64; t++) {
        __syncthreads();
        const float4* Ksrc = (const float4*)(Kb + (size_t)t * 64 * DK);
        const float4* Vsrc = (const float4*)(Vb + (size_t)t * 64 * DK);
        #pragma unroll
        for (int i = 0; i < 8; i++) {
            int idx = tid + i * 128;
            ((float4*)Ks)[idx] = Ksrc[idx];
            ((float4*)Vs)[idx] = Vsrc[idx];
        }
        __syncthreads();

        #pragma unroll 2
        for (int j = 0; j < 64; j++) {
            float s = 0.f;
            #pragma unroll
            for (int d4 = 0; d4 < DK; d4 += 4) {
                float4 kv = *(const float4*)&Ks[j][d4];
                s += q[d4 + 0] * kv.x + q[d4 + 1] * kv.y
                   + q[d4 + 2] * kv.z + q[d4 + 3] * kv.w;
            }
            s *= scale;
            if (s > mrun) {
                float corr = __expf(mrun - s);
                mrun = s;
                lrun *= corr;
                #pragma unroll
                for (int d = 0; d < DK; d++) o[d] *= corr;
            }
            float p = __expf(s - mrun);
            lrun += p;
            #pragma unroll
            for (int d4 = 0; d4 < DK; d4 += 4) {
                float4 vv = *(const float4*)&Vs[j][d4];
                o[d4 + 0] += p * vv.x;
                o[d4 + 1] += p * vv.y;
                o[d4 + 2] += p * vv.z;
                o[d4 + 3] += p * vv.w;
            }
        }
    }

    const float inv = 1.0f / lrun;
    const int b = bh >> 4;
    const int h = bh & 15;
    float* optr = &g_ATT[((size_t)b * SEQ + qidx) * DM + h * DK];
    #pragma unroll
    for (int d4 = 0; d4 < DK; d4 += 4) {
        float4 v;
        v.x = o[d4 + 0] * inv;
        v.y = o[d4 + 1] * inv;
        v.z = o[d4 + 2] * inv;
        v.w = o[d4 + 3] * inv;
        *(float4*)&optr[d4] = v;
    }
}

// ---------------------------------------------------------------------------
extern "C" void kernel_launch(void* const* d_in, const int* in_sizes, int n_in,
                              void* d_out, int out_size)
{
    const float* x  = (const float*)d_in[0];
    const float* Wq = (const float*)d_in[1];
    const float* bq = (const float*)d_in[2];
    const float* Wk = (const float*)d_in[3];
    const float* bk = (const float*)d_in[4];
    const float* Wv = (const float*)d_in[5];
    const float* bv = (const float*)d_in[6];
    const float* Wo = (const float*)d_in[7];
    const float* bo = (const float*)d_in[8];
    float* out = (float*)d_out;

    cudaFuncSetAttribute(gemm_mma, cudaFuncAttributeMaxDynamicSharedMemorySize,
                         GEMM_SMEM);

    // 1) QKV projections (tf32 mma.sync) -> split-head scratch
    dim3 gq(DM / 128, MROWS / 128, 3);
    gemm_mma<<<gq, 256, GEMM_SMEM>>>(x, Wq, Wk, Wv, bq, bk, bv, nullptr, 0);

    // 2) Flash attention -> g_ATT [b,s,h*64+d]
    mha_flash<<<BATCH * HEADS * (SEQ / 128), 128>>>();

    // 3) Output projection (tf32 mma.sync), reads g_ATT
    dim3 go(DM / 128, MROWS / 128, 1);
    gemm_mma<<<go, 256, GEMM_SMEM>>>(nullptr, Wo, nullptr, nullptr, bo, nullptr, nullptr,
                                     out, 1);
}

// round 11
// speedup vs baseline: 3.9508x; 2.8843x over previous
#include <cuda_runtime.h>
#include <math.h>
#include <stdint.h>

// Shapes (fixed by the problem)
#define BATCH 2
#define SEQ   2048
#define DM    1024
#define HEADS 16
#define DK    64
#define MROWS (BATCH * SEQ)          // 4096
#define LOG2E 1.44269504088896340736f

// Scratch: device globals (allocation-free rule)
__device__ float g_Q[BATCH * HEADS * SEQ * DK];     // [b,h,s,d] tf32 bits, pre-scaled 1/8
__device__ float g_K[BATCH * HEADS * SEQ * DK];     // tf32 bits
__device__ float g_V[BATCH * HEADS * SEQ * DK];     // tf32 bits
__device__ float g_ATT[MROWS * DM];                 // [b,s, h*64+d] fp32

__device__ __forceinline__ float to_tf32(float x) {
    float y;
    asm("cvt.rna.tf32.f32 %0, %1;" : "=f"(y) : "f"(x));
    return y;
}
__device__ __forceinline__ float exp2a(float x) {
    float y;
    asm("ex2.approx.f32 %0, %1;" : "=f"(y) : "f"(x));
    return y;
}
__device__ __forceinline__ void mma_tf32(float* c, const uint32_t* a, const uint32_t* b) {
    asm volatile(
        "mma.sync.aligned.m16n8k8.row.col.f32.tf32.tf32.f32 "
        "{%0,%1,%2,%3}, {%4,%5,%6,%7}, {%8,%9}, {%0,%1,%2,%3};"
        : "+f"(c[0]), "+f"(c[1]), "+f"(c[2]), "+f"(c[3])
        : "r"(a[0]), "r"(a[1]), "r"(a[2]), "r"(a[3]), "r"(b[0]), "r"(b[1]));
}
__device__ __forceinline__ uint32_t smem_u32(const void* p) {
    uint32_t a;
    asm("{ .reg .u64 t; cvta.to.shared.u64 t, %1; cvt.u32.u64 %0, t; }"
        : "=r"(a) : "l"(p));
    return a;
}
__device__ __forceinline__ void cp16(uint32_t dst, const float* src) {
    asm volatile("cp.async.cg.shared.global [%0], [%1], 16;" :: "r"(dst), "l"(src));
}
__device__ __forceinline__ void cp_commit() { asm volatile("cp.async.commit_group;" ::: "memory"); }
__device__ __forceinline__ void cp_wait0()  { asm volatile("cp.async.wait_group 0;" ::: "memory"); }

// ---------------------------------------------------------------------------
// mma.sync tf32 GEMM: C[4096,1024] = A @ W + bias.
// CTA tile 128x128, 256 threads = 2(m) x 4(n) warps; warp tile 64x32.
// ---------------------------------------------------------------------------
#define A_STRIDE 36
#define B_STRIDE 136
#define A_FLOATS (128 * A_STRIDE)
#define B_FLOATS (32 * B_STRIDE)
#define BUF_FLOATS (A_FLOATS + B_FLOATS)
#define OFF_BIAS 0
#define OFF_A    128
#define GEMM_SMEM ((128 + 2 * BUF_FLOATS) * 4)   // 72192 bytes

__global__ __launch_bounds__(256, 1) void gemm_mma(
    const float* __restrict__ Ain,
    const float* __restrict__ W0, const float* __restrict__ W1, const float* __restrict__ W2,
    const float* __restrict__ b0, const float* __restrict__ b1, const float* __restrict__ b2,
    float* __restrict__ Cout, int isOut)
{
    extern __shared__ float smem[];

    const int z = blockIdx.z;
    const float* A    = isOut ? g_ATT : Ain;
    const float* W    = isOut ? W0 : (z == 0) ? W0 : (z == 1) ? W1 : W2;
    const float* bias = isOut ? b0 : (z == 0) ? b0 : (z == 1) ? b1 : b2;

    const int tid  = threadIdx.x;
    const int wid  = tid >> 5;
    const int lane = tid & 31;
    const int wm   = wid >> 2;
    const int wn   = wid & 3;
    const int g    = lane >> 2;
    const int tig  = lane & 3;

    const int bm = blockIdx.y * 128;
    const int bn = blockIdx.x * 128;

    if (tid < 128) smem[OFF_BIAS + tid] = bias[bn + tid];

    const int a_row = tid >> 3;
    const int a_kf  = tid & 7;
    const int b_n4  = tid & 31;

    float4 pa[4], pb[4];

    #pragma unroll
    for (int j = 0; j < 4; j++) {
        pa[j] = *(const float4*)&A[(size_t)(bm + a_row + j * 32) * DM + a_kf * 4];
        pb[j] = *(const float4*)&W[(size_t)((tid >> 5) + j * 8) * DM + bn + b_n4 * 4];
    }
    {
        float* As = smem + OFF_A;
        float* Bs = As + A_FLOATS;
        #pragma unroll
        for (int j = 0; j < 4; j++) {
            float* pA = &As[(a_row + j * 32) * A_STRIDE + a_kf * 4];
            pA[0] = to_tf32(pa[j].x); pA[1] = to_tf32(pa[j].y);
            pA[2] = to_tf32(pa[j].z); pA[3] = to_tf32(pa[j].w);
            float* pB = &Bs[((tid >> 5) + j * 8) * B_STRIDE + b_n4 * 4];
            pB[0] = to_tf32(pb[j].x); pB[1] = to_tf32(pb[j].y);
            pB[2] = to_tf32(pb[j].z); pB[3] = to_tf32(pb[j].w);
        }
    }
    __syncthreads();

    float c[4][4][4] = {};

    for (int i = 0; i < 32; i++) {
        if (i < 31) {
            const int k0 = (i + 1) * 32;
            #pragma unroll
            for (int j = 0; j < 4; j++) {
                pa[j] = *(const float4*)&A[(size_t)(bm + a_row + j * 32) * DM + k0 + a_kf * 4];
                pb[j] = *(const float4*)&W[(size_t)(k0 + (tid >> 5) + j * 8) * DM + bn + b_n4 * 4];
            }
        }

        const float* As = smem + OFF_A + (i & 1) * BUF_FLOATS;
        const float* Bs = As + A_FLOATS;
        #pragma unroll
        for (int q = 0; q < 4; q++) {
            uint32_t af[4][4], bf[4][2];
            #pragma unroll
            for (int mf = 0; mf < 4; mf++) {
                const uint32_t* base = (const uint32_t*)&As[(wm * 64 + mf * 16 + g) * A_STRIDE + q * 8 + tig];
                af[mf][0] = base[0];
                af[mf][1] = base[8 * A_STRIDE];
                af[mf][2] = base[4];
                af[mf][3] = base[8 * A_STRIDE + 4];
            }
            #pragma unroll
            for (int nf = 0; nf < 4; nf++) {
                const uint32_t* base = (const uint32_t*)&Bs[(q * 8 + tig) * B_STRIDE + wn * 32 + nf * 8 + g];
                bf[nf][0] = base[0];
                bf[nf][1] = base[4 * B_STRIDE];
            }
            #pragma unroll
            for (int mf = 0; mf < 4; mf++)
                #pragma unroll
                for (int nf = 0; nf < 4; nf++)
                    mma_tf32(c[mf][nf], af[mf], bf[nf]);
        }

        if (i < 31) {
            float* Asn = smem + OFF_A + ((i + 1) & 1) * BUF_FLOATS;
            float* Bsn = Asn + A_FLOATS;
            #pragma unroll
            for (int j = 0; j < 4; j++) {
                float* pA = &Asn[(a_row + j * 32) * A_STRIDE + a_kf * 4];
                pA[0] = to_tf32(pa[j].x); pA[1] = to_tf32(pa[j].y);
                pA[2] = to_tf32(pa[j].z); pA[3] = to_tf32(pa[j].w);
                float* pB = &Bsn[((tid >> 5) + j * 8) * B_STRIDE + b_n4 * 4];
                pB[0] = to_tf32(pb[j].x); pB[1] = to_tf32(pb[j].y);
                pB[2] = to_tf32(pb[j].z); pB[3] = to_tf32(pb[j].w);
            }
            __syncthreads();
        }
    }

    // epilogue: bias (+ tf32 convert & Q pre-scale when writing QKV scratch)
    float* O = isOut ? Cout : (z == 0) ? g_Q : (z == 1) ? g_K : g_V;
    const float qsc = (!isOut && z == 0) ? 0.125f : 1.0f;

    #pragma unroll
    for (int mf = 0; mf < 4; mf++) {
        const int row = bm + wm * 64 + mf * 16 + g;
        #pragma unroll
        for (int nf = 0; nf < 4; nf++) {
            const int colt = wn * 32 + nf * 8 + tig * 2;
            const float bx = smem[OFF_BIAS + colt];
            const float by = smem[OFF_BIAS + colt + 1];
            size_t base0, base1;
            if (isOut) {
                base0 = (size_t)row * DM + bn + colt;
                base1 = (size_t)(row + 8) * DM + bn + colt;
            } else {
                const int col = bn + colt;
                const int h = col >> 6, d0 = col & 63;
                const int b_ = row >> 11;
                const int s0 = row & 2047;
                base0 = ((size_t)(b_ * HEADS + h) * SEQ + s0) * DK + d0;
                base1 = base0 + 8 * DK;
            }
            float2 v0 = { c[mf][nf][0] + bx, c[mf][nf][1] + by };
            float2 v1 = { c[mf][nf][2] + bx, c[mf][nf][3] + by };
            if (!isOut) {
                v0.x = to_tf32(v0.x * qsc); v0.y = to_tf32(v0.y * qsc);
                v1.x = to_tf32(v1.x * qsc); v1.y = to_tf32(v1.y * qsc);
            }
            *(float2*)&O[base0] = v0;
            *(float2*)&O[base1] = v1;
        }
    }
}

// ---------------------------------------------------------------------------
// Flash attention on mma.sync tf32.
// CTA: 128 threads (4 warps), 64 queries of one (b,h); warp = 16 query rows.
// KV tiles of 64 keys, double-buffered cp.async.
// K smem stride 68 (b-frag bank = 4g+tig, conflict-free);
// V smem stride 72 (b-frag bank = 8tig+g, conflict-free).
// P (probabilities) re-laid out C-frag -> A-frag via per-warp smem buffer.
// ---------------------------------------------------------------------------
#define KSTR 68
#define VSTR 72
#define PSTR 68
#define KBUF (64 * KSTR)             // 4352 floats
#define VBUF (64 * VSTR)             // 4608 floats
#define PBUF (16 * PSTR)             // 1088 floats per warp
#define FLASH_SMEM ((2 * KBUF + 2 * VBUF + 4 * PBUF) * 4)   // 89088 bytes

__global__ __launch_bounds__(128, 2) void flash_mma()
{
    extern __shared__ float fs[];
    const int tid  = threadIdx.x;
    const int wid  = tid >> 5;
    const int lane = tid & 31;
    const int g    = lane >> 2;
    const int tig  = lane & 3;

    const int bh = blockIdx.y;                 // 0..31
    const int qb = blockIdx.x * 64;            // query base

    const float* Qg = g_Q + (size_t)bh * SEQ * DK;
    const float* Kg = g_K + (size_t)bh * SEQ * DK;
    const float* Vg = g_V + (size_t)bh * SEQ * DK;

    float* Pw = fs + 2 * KBUF + 2 * VBUF + wid * PBUF;
    const uint32_t sb = smem_u32(fs);

    // Q fragments: rows qb + wid*16 + {g, g+8}, persistent in registers
    uint32_t qa[8][4];
    {
        const int r0 = qb + wid * 16 + g;
        #pragma unroll
        for (int ks = 0; ks < 8; ks++) {
            qa[ks][0] = __float_as_uint(Qg[(size_t)r0 * DK + ks * 8 + tig]);
            qa[ks][1] = __float_as_uint(Qg[(size_t)(r0 + 8) * DK + ks * 8 + tig]);
            qa[ks][2] = __float_as_uint(Qg[(size_t)r0 * DK + ks * 8 + tig + 4]);
            qa[ks][3] = __float_as_uint(Qg[(size_t)(r0 + 8) * DK + ks * 8 + tig + 4]);
        }
    }

    float o[8][4] = {};
    float mr0 = -INFINITY, mr1 = -INFINITY;
    float l0 = 0.f, l1 = 0.f;

    // tile loader: K 1024 float4 + V 1024 float4, 8+8 per thread
    auto load_tile = [&](int t) {
        const int buf = t & 1;
        const float* Ksrc = Kg + (size_t)t * 64 * DK;
        const float* Vsrc = Vg + (size_t)t * 64 * DK;
        const uint32_t kd = sb + buf * KBUF * 4;
        const uint32_t vd = sb + (2 * KBUF + buf * VBUF) * 4;
        #pragma unroll
        for (int i = 0; i < 8; i++) {
            int idx = tid + i * 128;
            int row = idx >> 4, c4 = idx & 15;
            cp16(kd + (row * KSTR + c4 * 4) * 4, Ksrc + row * 64 + c4 * 4);
        }
        #pragma unroll
        for (int i = 0; i < 8; i++) {
            int idx = tid + i * 128;
            int row = idx >> 4, c4 = idx & 15;
            cp16(vd + (row * VSTR + c4 * 4) * 4, Vsrc + row * 64 + c4 * 4);
        }
    };

    load_tile(0);
    cp_commit();

    #pragma unroll 1
    for (int t = 0; t < SEQ / 64; t++) {
        cp_wait0();
        __syncthreads();
        if (t + 1 < SEQ / 64) {
            load_tile(t + 1);
            cp_commit();
        }

        const float* Kt = fs + (t & 1) * KBUF;
        const float* Vt = fs + 2 * KBUF + (t & 1) * VBUF;

        // ---- S = Q K^T (scores already scaled: Q pre-scaled by 1/8)
        float s[8][4] = {};
        #pragma unroll
        for (int ks = 0; ks < 8; ks++) {
            #pragma unroll
            for (int nt = 0; nt < 8; nt++) {
                const uint32_t* bp = (const uint32_t*)&Kt[(nt * 8 + g) * KSTR + ks * 8 + tig];
                uint32_t b[2] = { bp[0], bp[4] };
                mma_tf32(s[nt], qa[ks], b);
            }
        }

        // ---- online softmax (rows g and g+8 of this warp's 16-row tile)
        float m0 = -INFINITY, m1 = -INFINITY;
        #pragma unroll
        for (int nt = 0; nt < 8; nt++) {
            m0 = fmaxf(m0, fmaxf(s[nt][0], s[nt][1]));
            m1 = fmaxf(m1, fmaxf(s[nt][2], s[nt][3]));
        }
        m0 = fmaxf(m0, __shfl_xor_sync(0xffffffffu, m0, 1));
        m0 = fmaxf(m0, __shfl_xor_sync(0xffffffffu, m0, 2));
        m1 = fmaxf(m1, __shfl_xor_sync(0xffffffffu, m1, 1));
        m1 = fmaxf(m1, __shfl_xor_sync(0xffffffffu, m1, 2));

        const float nm0 = fmaxf(mr0, m0), nm1 = fmaxf(mr1, m1);
        const float corr0 = exp2a((mr0 - nm0) * LOG2E);
        const float corr1 = exp2a((mr1 - nm1) * LOG2E);
        mr0 = nm0; mr1 = nm1;
        const float c0 = nm0 * LOG2E, c1 = nm1 * LOG2E;

        float t0 = 0.f, t1 = 0.f;
        #pragma unroll
        for (int nt = 0; nt < 8; nt++) {
            float p0 = to_tf32(exp2a(fmaf(s[nt][0], LOG2E, -c0)));
            float p1 = to_tf32(exp2a(fmaf(s[nt][1], LOG2E, -c0)));
            float p2 = to_tf32(exp2a(fmaf(s[nt][2], LOG2E, -c1)));
            float p3 = to_tf32(exp2a(fmaf(s[nt][3], LOG2E, -c1)));
            s[nt][0] = p0; s[nt][1] = p1; s[nt][2] = p2; s[nt][3] = p3;
            t0 += p0 + p1;
            t1 += p2 + p3;
        }
        t0 += __shfl_xor_sync(0xffffffffu, t0, 1);
        t0 += __shfl_xor_sync(0xffffffffu, t0, 2);
        t1 += __shfl_xor_sync(0xffffffffu, t1, 1);
        t1 += __shfl_xor_sync(0xffffffffu, t1, 2);
        l0 = l0 * corr0 + t0;
        l1 = l1 * corr1 + t1;

        #pragma unroll
        for (int nd = 0; nd < 8; nd++) {
            o[nd][0] *= corr0; o[nd][1] *= corr0;
            o[nd][2] *= corr1; o[nd][3] *= corr1;
        }

        // ---- P: C-frag -> A-frag via per-warp smem
        #pragma unroll
        for (int nt = 0; nt < 8; nt++) {
            *(float2*)&Pw[g * PSTR + nt * 8 + 2 * tig]       = make_float2(s[nt][0], s[nt][1]);
            *(float2*)&Pw[(g + 8) * PSTR + nt * 8 + 2 * tig] = make_float2(s[nt][2], s[nt][3]);
        }
        __syncwarp();

        // ---- O += P V
        #pragma unroll
        for (int ks = 0; ks < 8; ks++) {
            uint32_t a[4];
            a[0] = __float_as_uint(Pw[g * PSTR + ks * 8 + tig]);
            a[1] = __float_as_uint(Pw[(g + 8) * PSTR + ks * 8 + tig]);
            a[2] = __float_as_uint(Pw[g * PSTR + ks * 8 + tig + 4]);
            a[3] = __float_as_uint(Pw[(g + 8) * PSTR + ks * 8 + tig + 4]);
            #pragma unroll
            for (int nd = 0; nd < 8; nd++) {
                const uint32_t* bp0 = (const uint32_t*)&Vt[(ks * 8 + tig) * VSTR + nd * 8 + g];
                const uint32_t* bp1 = (const uint32_t*)&Vt[(ks * 8 + tig + 4) * VSTR + nd * 8 + g];
                uint32_t b[2] = { bp0[0], bp1[0] };
                mma_tf32(o[nd], a, b);
            }
        }
    }

    // ---- epilogue: normalize and store to g_ATT [b,s, h*64+d]
    const float i0 = 1.0f / l0;
    const float i1 = 1.0f / l1;
    const int b_ = bh >> 4;
    const int h  = bh & 15;
    const int s0 = qb + wid * 16 + g;
    float* O0 = &g_ATT[((size_t)b_ * SEQ + s0) * DM + h * DK];
    float* O1 = &g_ATT[((size_t)b_ * SEQ + s0 + 8) * DM + h * DK];
    #pragma unroll
    for (int nd = 0; nd < 8; nd++) {
        *(float2*)&O0[nd * 8 + 2 * tig] = make_float2(o[nd][0] * i0, o[nd][1] * i0);
        *(float2*)&O1[nd * 8 + 2 * tig] = make_float2(o[nd][2] * i1, o[nd][3] * i1);
    }
}

// ---------------------------------------------------------------------------
extern "C" void kernel_launch(void* const* d_in, const int* in_sizes, int n_in,
                              void* d_out, int out_size)
{
    const float* x  = (const float*)d_in[0];
    const float* Wq = (const float*)d_in[1];
    const float* bq = (const float*)d_in[2];
    const float* Wk = (const float*)d_in[3];
    const float* bk = (const float*)d_in[4];
    const float* Wv = (const float*)d_in[5];
    const float* bv = (const float*)d_in[6];
    const float* Wo = (const float*)d_in[7];
    const float* bo = (const float*)d_in[8];
    float* out = (float*)d_out;

    cudaFuncSetAttribute(gemm_mma, cudaFuncAttributeMaxDynamicSharedMemorySize,
                         GEMM_SMEM);
    cudaFuncSetAttribute(flash_mma, cudaFuncAttributeMaxDynamicSharedMemorySize,
                         FLASH_SMEM);

    // 1) QKV projections -> split-head scratch (tf32 bits, Q pre-scaled 1/8)
    dim3 gq(DM / 128, MROWS / 128, 3);
    gemm_mma<<<gq, 256, GEMM_SMEM>>>(x, Wq, Wk, Wv, bq, bk, bv, nullptr, 0);

    // 2) Flash attention (tensor-core) -> g_ATT
    dim3 gf(SEQ / 64, BATCH * HEADS, 1);
    flash_mma<<<gf, 128, FLASH_SMEM>>>();

    // 3) Output projection, reads g_ATT
    dim3 go(DM / 128, MROWS / 128, 1);
    gemm_mma<<<go, 256, GEMM_SMEM>>>(nullptr, Wo, nullptr, nullptr, bo, nullptr, nullptr,
                                     out, 1);
}

// round 12
// speedup vs baseline: 4.3339x; 1.0970x over previous
#include <cuda_runtime.h>
#include <math.h>
#include <stdint.h>

// Shapes (fixed by the problem)
#define BATCH 2
#define SEQ   2048
#define DM    1024
#define HEADS 16
#define DK    64
#define MROWS (BATCH * SEQ)          // 4096
#define LOG2E 1.44269504088896340736f

// Scratch: device globals (allocation-free rule). All hold tf32-rounded bits.
__device__ float g_X[MROWS * DM];                   // x, tf32 bits
__device__ float g_W[4 * DM * DM];                  // Wq|Wk|Wv|Wo, tf32 bits
__device__ float g_Q[BATCH * HEADS * SEQ * DK];     // [b,h,s,d] tf32 bits, pre-scaled 1/8
__device__ float g_K[BATCH * HEADS * SEQ * DK];     // tf32 bits
__device__ float g_V[BATCH * HEADS * SEQ * DK];     // tf32 bits
__device__ float g_ATT[MROWS * DM];                 // [b,s, h*64+d] tf32 bits

__device__ __forceinline__ float to_tf32(float x) {
    float y;
    asm("cvt.rna.tf32.f32 %0, %1;" : "=f"(y) : "f"(x));
    return y;
}
__device__ __forceinline__ float exp2a(float x) {
    float y;
    asm("ex2.approx.f32 %0, %1;" : "=f"(y) : "f"(x));
    return y;
}
__device__ __forceinline__ void mma_tf32(float* c, const uint32_t* a, const uint32_t* b) {
    asm volatile(
        "mma.sync.aligned.m16n8k8.row.col.f32.tf32.tf32.f32 "
        "{%0,%1,%2,%3}, {%4,%5,%6,%7}, {%8,%9}, {%0,%1,%2,%3};"
        : "+f"(c[0]), "+f"(c[1]), "+f"(c[2]), "+f"(c[3])
        : "r"(a[0]), "r"(a[1]), "r"(a[2]), "r"(a[3]), "r"(b[0]), "r"(b[1]));
}
__device__ __forceinline__ uint32_t smem_u32(const void* p) {
    uint32_t a;
    asm("{ .reg .u64 t; cvta.to.shared.u64 t, %1; cvt.u32.u64 %0, t; }"
        : "=r"(a) : "l"(p));
    return a;
}
__device__ __forceinline__ void cp16(uint32_t dst, const float* src) {
    asm volatile("cp.async.cg.shared.global [%0], [%1], 16;" :: "r"(dst), "l"(src));
}
__device__ __forceinline__ void cp_commit() { asm volatile("cp.async.commit_group;" ::: "memory"); }
__device__ __forceinline__ void cp_wait0()  { asm volatile("cp.async.wait_group 0;" ::: "memory"); }
__device__ __forceinline__ void cp_wait2()  { asm volatile("cp.async.wait_group 2;" ::: "memory"); }

// ---------------------------------------------------------------------------
// tf32 pre-convert: x -> g_X, {Wq,Wk,Wv,Wo} -> g_W (RNA rounding once).
// 2M float4 total.
// ---------------------------------------------------------------------------
__global__ __launch_bounds__(256) void convert_tf32(
    const float* __restrict__ x,
    const float* __restrict__ wq, const float* __restrict__ wk,
    const float* __restrict__ wv, const float* __restrict__ wo)
{
    const size_t idx = (size_t)blockIdx.x * 256 + threadIdx.x;   // float4 index
    const float* src;
    float* dst;
    size_t off;
    if (idx < (1u << 20)) {                       // x: 4M floats = 1M float4
        src = x; dst = g_X; off = idx;
    } else {
        const size_t r = idx - (1u << 20);
        const size_t w = r >> 18;                 // each W: 256K float4
        off = r & ((1u << 18) - 1);
        src = (w == 0) ? wq : (w == 1) ? wk : (w == 2) ? wv : wo;
        dst = g_W + (w << 20);
    }
    float4 v = ((const float4*)src)[off];
    v.x = to_tf32(v.x); v.y = to_tf32(v.y);
    v.z = to_tf32(v.z); v.w = to_tf32(v.w);
    ((float4*)dst)[off] = v;
}

// ---------------------------------------------------------------------------
// tf32 GEMM: C[4096,1024] = A @ W + bias; inputs pre-converted tf32 bits.
// CTA tile 128x128, 256 threads = 2(m) x 4(n) warps; warp tile 64x32.
// 4-stage cp.async pipeline, K-chunk 16. 2 CTAs/SM.
// ---------------------------------------------------------------------------
#define AST 20               // A floats per m-row (80B, 16B aligned)
#define BST 136              // B floats per k-row (544B, 16B aligned)
#define A_F (128 * AST)      // 2560 floats
#define B_F (16 * BST)       // 2176 floats
#define STG_F (A_F + B_F)    // 4736 floats (18944B, 16B aligned)
#define NSTG 4
#define OFF_A 128
#define GEMM_SMEM ((OFF_A + NSTG * STG_F) * 4)     // 76288 bytes

__global__ __launch_bounds__(256, 2) void gemm_mma(
    const float* __restrict__ b0, const float* __restrict__ b1,
    const float* __restrict__ b2, float* __restrict__ Cout, int isOut)
{
    extern __shared__ float smem[];

    const int z = blockIdx.z;
    const float* A    = isOut ? g_ATT : g_X;
    const float* W    = isOut ? (g_W + 3u * (1u << 20)) : (g_W + (size_t)z * (1u << 20));
    const float* bias = isOut ? b0 : (z == 0) ? b0 : (z == 1) ? b1 : b2;

    const int tid  = threadIdx.x;
    const int wid  = tid >> 5;
    const int lane = tid & 31;
    const int wm   = wid >> 2;
    const int wn   = wid & 3;
    const int g    = lane >> 2;
    const int tig  = lane & 3;

    const int bm = blockIdx.y * 128;
    const int bn = blockIdx.x * 128;

    if (tid < 128) smem[tid] = bias[bn + tid];

    const uint32_t sb = smem_u32(smem);
    const int arow = tid >> 2, ac4 = tid & 3;        // slot j: +64 rows
    const int brow = tid >> 5, bn4 = tid & 31;       // slot j: +8 rows

    // issue one K-chunk (16 k) into stage s
    auto issue = [&](int c, int s) {
        const int k0 = c * 16;
        const uint32_t ab = sb + (OFF_A + s * STG_F) * 4;
        const uint32_t bb = ab + A_F * 4;
        #pragma unroll
        for (int j = 0; j < 2; j++) {
            cp16(ab + ((arow + j * 64) * AST + ac4 * 4) * 4,
                 &A[(size_t)(bm + arow + j * 64) * DM + k0 + ac4 * 4]);
            cp16(bb + ((brow + j * 8) * BST + bn4 * 4) * 4,
                 &W[(size_t)(k0 + brow + j * 8) * DM + bn + bn4 * 4]);
        }
        cp_commit();
    };

    issue(0, 0); issue(1, 1); issue(2, 2);

    float c[4][4][4] = {};

    #pragma unroll 1
    for (int i = 0; i < 64; i++) {
        cp_wait2();
        __syncthreads();
        if (i < 61) issue(i + 3, (i + 3) & 3);

        const float* As = smem + OFF_A + (i & 3) * STG_F;
        const float* Bs = As + A_F;
        #pragma unroll
        for (int q = 0; q < 2; q++) {
            uint32_t af[4][4], bf[4][2];
            #pragma unroll
            for (int mf = 0; mf < 4; mf++) {
                const uint32_t* base = (const uint32_t*)&As[(wm * 64 + mf * 16 + g) * AST + q * 8 + tig];
                af[mf][0] = base[0];
                af[mf][1] = base[8 * AST];
                af[mf][2] = base[4];
                af[mf][3] = base[8 * AST + 4];
            }
            #pragma unroll
            for (int nf = 0; nf < 4; nf++) {
                const uint32_t* base = (const uint32_t*)&Bs[(q * 8 + tig) * BST + wn * 32 + nf * 8 + g];
                bf[nf][0] = base[0];
                bf[nf][1] = base[4 * BST];
            }
            #pragma unroll
            for (int mf = 0; mf < 4; mf++)
                #pragma unroll
                for (int nf = 0; nf < 4; nf++)
                    mma_tf32(c[mf][nf], af[mf], bf[nf]);
        }
    }

    // epilogue: bias (+ tf32 convert & Q pre-scale when writing QKV scratch)
    float* O = isOut ? Cout : (z == 0) ? g_Q : (z == 1) ? g_K : g_V;
    const float qsc = (!isOut && z == 0) ? 0.125f : 1.0f;

    #pragma unroll
    for (int mf = 0; mf < 4; mf++) {
        const int row = bm + wm * 64 + mf * 16 + g;
        #pragma unroll
        for (int nf = 0; nf < 4; nf++) {
            const int colt = wn * 32 + nf * 8 + tig * 2;
            const float bx = smem[colt];
            const float by = smem[colt + 1];
            size_t base0, base1;
            if (isOut) {
                base0 = (size_t)row * DM + bn + colt;
                base1 = (size_t)(row + 8) * DM + bn + colt;
            } else {
                const int col = bn + colt;
                const int h = col >> 6, d0 = col & 63;
                const int b_ = row >> 11;
                const int s0 = row & 2047;
                base0 = ((size_t)(b_ * HEADS + h) * SEQ + s0) * DK + d0;
                base1 = base0 + 8 * DK;
            }
            float2 v0 = { c[mf][nf][0] + bx, c[mf][nf][1] + by };
            float2 v1 = { c[mf][nf][2] + bx, c[mf][nf][3] + by };
            if (!isOut) {
                v0.x = to_tf32(v0.x * qsc); v0.y = to_tf32(v0.y * qsc);
                v1.x = to_tf32(v1.x * qsc); v1.y = to_tf32(v1.y * qsc);
            }
            *(float2*)&O[base0] = v0;
            *(float2*)&O[base1] = v1;
        }
    }
}

// ---------------------------------------------------------------------------
// Flash attention on mma.sync tf32 (as R11-passing version), epilogue now
// writes tf32 bits so the out-projection can cp.async g_ATT directly.
// ---------------------------------------------------------------------------
#define KSTR 68
#define VSTR 72
#define PSTR 68
#define KBUF (64 * KSTR)
#define VBUF (64 * VSTR)
#define PBUF (16 * PSTR)
#define FLASH_SMEM ((2 * KBUF + 2 * VBUF + 4 * PBUF) * 4)   // 89088 bytes

__global__ __launch_bounds__(128, 2) void flash_mma()
{
    extern __shared__ float fs[];
    const int tid  = threadIdx.x;
    const int wid  = tid >> 5;
    const int lane = tid & 31;
    const int g    = lane >> 2;
    const int tig  = lane & 3;

    const int bh = blockIdx.y;
    const int qb = blockIdx.x * 64;

    const float* Qg = g_Q + (size_t)bh * SEQ * DK;
    const float* Kg = g_K + (size_t)bh * SEQ * DK;
    const float* Vg = g_V + (size_t)bh * SEQ * DK;

    float* Pw = fs + 2 * KBUF + 2 * VBUF + wid * PBUF;
    const uint32_t sb = smem_u32(fs);

    uint32_t qa[8][4];
    {
        const int r0 = qb + wid * 16 + g;
        #pragma unroll
        for (int ks = 0; ks < 8; ks++) {
            qa[ks][0] = __float_as_uint(Qg[(size_t)r0 * DK + ks * 8 + tig]);
            qa[ks][1] = __float_as_uint(Qg[(size_t)(r0 + 8) * DK + ks * 8 + tig]);
            qa[ks][2] = __float_as_uint(Qg[(size_t)r0 * DK + ks * 8 + tig + 4]);
            qa[ks][3] = __float_as_uint(Qg[(size_t)(r0 + 8) * DK + ks * 8 + tig + 4]);
        }
    }

    float o[8][4] = {};
    float mr0 = -INFINITY, mr1 = -INFINITY;
    float l0 = 0.f, l1 = 0.f;

    auto load_tile = [&](int t) {
        const int buf = t & 1;
        const float* Ksrc = Kg + (size_t)t * 64 * DK;
        const float* Vsrc = Vg + (size_t)t * 64 * DK;
        const uint32_t kd = sb + buf * KBUF * 4;
        const uint32_t vd = sb + (2 * KBUF + buf * VBUF) * 4;
        #pragma unroll
        for (int i = 0; i < 8; i++) {
            int idx = tid + i * 128;
            int row = idx >> 4, c4 = idx & 15;
            cp16(kd + (row * KSTR + c4 * 4) * 4, Ksrc + row * 64 + c4 * 4);
        }
        #pragma unroll
        for (int i = 0; i < 8; i++) {
            int idx = tid + i * 128;
            int row = idx >> 4, c4 = idx & 15;
            cp16(vd + (row * VSTR + c4 * 4) * 4, Vsrc + row * 64 + c4 * 4);
        }
    };

    load_tile(0);
    cp_commit();

    #pragma unroll 1
    for (int t = 0; t < SEQ / 64; t++) {
        cp_wait0();
        __syncthreads();
        if (t + 1 < SEQ / 64) {
            load_tile(t + 1);
            cp_commit();
        }

        const float* Kt = fs + (t & 1) * KBUF;
        const float* Vt = fs + 2 * KBUF + (t & 1) * VBUF;

        float s[8][4] = {};
        #pragma unroll
        for (int ks = 0; ks < 8; ks++) {
            #pragma unroll
            for (int nt = 0; nt < 8; nt++) {
                const uint32_t* bp = (const uint32_t*)&Kt[(nt * 8 + g) * KSTR + ks * 8 + tig];
                uint32_t b[2] = { bp[0], bp[4] };
                mma_tf32(s[nt], qa[ks], b);
            }
        }

        float m0 = -INFINITY, m1 = -INFINITY;
        #pragma unroll
        for (int nt = 0; nt < 8; nt++) {
            m0 = fmaxf(m0, fmaxf(s[nt][0], s[nt][1]));
            m1 = fmaxf(m1, fmaxf(s[nt][2], s[nt][3]));
        }
        m0 = fmaxf(m0, __shfl_xor_sync(0xffffffffu, m0, 1));
        m0 = fmaxf(m0, __shfl_xor_sync(0xffffffffu, m0, 2));
        m1 = fmaxf(m1, __shfl_xor_sync(0xffffffffu, m1, 1));
        m1 = fmaxf(m1, __shfl_xor_sync(0xffffffffu, m1, 2));

        const float nm0 = fmaxf(mr0, m0), nm1 = fmaxf(mr1, m1);
        const float corr0 = exp2a((mr0 - nm0) * LOG2E);
        const float corr1 = exp2a((mr1 - nm1) * LOG2E);
        mr0 = nm0; mr1 = nm1;
        const float c0 = nm0 * LOG2E, c1 = nm1 * LOG2E;

        float t0 = 0.f, t1 = 0.f;
        #pragma unroll
        for (int nt = 0; nt < 8; nt++) {
            float p0 = to_tf32(exp2a(fmaf(s[nt][0], LOG2E, -c0)));
            float p1 = to_tf32(exp2a(fmaf(s[nt][1], LOG2E, -c0)));
            float p2 = to_tf32(exp2a(fmaf(s[nt][2], LOG2E, -c1)));
            float p3 = to_tf32(exp2a(fmaf(s[nt][3], LOG2E, -c1)));
            s[nt][0] = p0; s[nt][1] = p1; s[nt][2] = p2; s[nt][3] = p3;
            t0 += p0 + p1;
            t1 += p2 + p3;
        }
        t0 += __shfl_xor_sync(0xffffffffu, t0, 1);
        t0 += __shfl_xor_sync(0xffffffffu, t0, 2);
        t1 += __shfl_xor_sync(0xffffffffu, t1, 1);
        t1 += __shfl_xor_sync(0xffffffffu, t1, 2);
        l0 = l0 * corr0 + t0;
        l1 = l1 * corr1 + t1;

        #pragma unroll
        for (int nd = 0; nd < 8; nd++) {
            o[nd][0] *= corr0; o[nd][1] *= corr0;
            o[nd][2] *= corr1; o[nd][3] *= corr1;
        }

        #pragma unroll
        for (int nt = 0; nt < 8; nt++) {
            *(float2*)&Pw[g * PSTR + nt * 8 + 2 * tig]       = make_float2(s[nt][0], s[nt][1]);
            *(float2*)&Pw[(g + 8) * PSTR + nt * 8 + 2 * tig] = make_float2(s[nt][2], s[nt][3]);
        }
        __syncwarp();

        #pragma unroll
        for (int ks = 0; ks < 8; ks++) {
            uint32_t a[4];
            a[0] = __float_as_uint(Pw[g * PSTR + ks * 8 + tig]);
            a[1] = __float_as_uint(Pw[(g + 8) * PSTR + ks * 8 + tig]);
            a[2] = __float_as_uint(Pw[g * PSTR + ks * 8 + tig + 4]);
            a[3] = __float_as_uint(Pw[(g + 8) * PSTR + ks * 8 + tig + 4]);
            #pragma unroll
            for (int nd = 0; nd < 8; nd++) {
                const uint32_t* bp0 = (const uint32_t*)&Vt[(ks * 8 + tig) * VSTR + nd * 8 + g];
                const uint32_t* bp1 = (const uint32_t*)&Vt[(ks * 8 + tig + 4) * VSTR + nd * 8 + g];
                uint32_t b[2] = { bp0[0], bp1[0] };
                mma_tf32(o[nd], a, b);
            }
        }
    }

    // epilogue: normalize, tf32-round, store to g_ATT [b,s, h*64+d]
    const float i0 = 1.0f / l0;
    const float i1 = 1.0f / l1;
    const int b_ = bh >> 4;
    const int h  = bh & 15;
    const int s0 = qb + wid * 16 + g;
    float* O0 = &g_ATT[((size_t)b_ * SEQ + s0) * DM + h * DK];
    float* O1 = &g_ATT[((size_t)b_ * SEQ + s0 + 8) * DM + h * DK];
    #pragma unroll
    for (int nd = 0; nd < 8; nd++) {
        *(float2*)&O0[nd * 8 + 2 * tig] =
            make_float2(to_tf32(o[nd][0] * i0), to_tf32(o[nd][1] * i0));
        *(float2*)&O1[nd * 8 + 2 * tig] =
            make_float2(to_tf32(o[nd][2] * i1), to_tf32(o[nd][3] * i1));
    }
}

// ---------------------------------------------------------------------------
extern "C" void kernel_launch(void* const* d_in, const int* in_sizes, int n_in,
                              void* d_out, int out_size)
{
    const float* x  = (const float*)d_in[0];
    const float* Wq = (const float*)d_in[1];
    const float* bq = (const float*)d_in[2];
    const float* Wk = (const float*)d_in[3];
    const float* bk = (const float*)d_in[4];
    const float* Wv = (const float*)d_in[5];
    const float* bv = (const float*)d_in[6];
    const float* Wo = (const float*)d_in[7];
    const float* bo = (const float*)d_in[8];
    float* out = (float*)d_out;

    cudaFuncSetAttribute(gemm_mma, cudaFuncAttributeMaxDynamicSharedMemorySize,
                         GEMM_SMEM);
    cudaFuncSetAttribute(flash_mma, cudaFuncAttributeMaxDynamicSharedMemorySize,
                         FLASH_SMEM);

    // 0) tf32 pre-convert: x -> g_X, W's -> g_W (2M float4)
    convert_tf32<<<8192, 256>>>(x, Wq, Wk, Wv, Wo);

    // 1) QKV projections -> split-head scratch (tf32 bits, Q pre-scaled 1/8)
    dim3 gq(DM / 128, MROWS / 128, 3);
    gemm_mma<<<gq, 256, GEMM_SMEM>>>(bq, bk, bv, nullptr, 0);

    // 2) Flash attention (tensor-core) -> g_ATT (tf32 bits)
    dim3 gf(SEQ / 64, BATCH * HEADS, 1);
    flash_mma<<<gf, 128, FLASH_SMEM>>>();

    // 3) Output projection, reads g_ATT/g_W
    dim3 go(DM / 128, MROWS / 128, 1);
    gemm_mma<<<go, 256, GEMM_SMEM>>>(bo, nullptr, nullptr, out, 1);
}

// round 14
// speedup vs baseline: 4.5296x; 1.0451x over previous
#include <cuda_runtime.h>
#include <math.h>
#include <stdint.h>

// Shapes (fixed by the problem)
#define BATCH 2
#define SEQ   2048
#define DM    1024
#define HEADS 16
#define DK    64
#define MROWS (BATCH * SEQ)          // 4096
#define LOG2E 1.44269504088896340736f

// Scratch: device globals (allocation-free rule). All hold tf32-rounded bits.
__device__ float g_X[MROWS * DM];                   // x, tf32 bits
__device__ float g_W[4 * DM * DM];                  // Wq|Wk|Wv|Wo, tf32 bits
__device__ float g_Q[BATCH * HEADS * SEQ * DK];     // [b,h,s,d] tf32 bits, pre-scaled 1/8
__device__ float g_K[BATCH * HEADS * SEQ * DK];     // tf32 bits
__device__ float g_V[BATCH * HEADS * SEQ * DK];     // tf32 bits
__device__ float g_ATT[MROWS * DM];                 // [b,s, h*64+d] tf32 bits

__device__ __forceinline__ float to_tf32(float x) {
    float y;
    asm("cvt.rna.tf32.f32 %0, %1;" : "=f"(y) : "f"(x));
    return y;
}
__device__ __forceinline__ float exp2a(float x) {
    float y;
    asm("ex2.approx.f32 %0, %1;" : "=f"(y) : "f"(x));
    return y;
}
__device__ __forceinline__ void mma_tf32(float* c, const uint32_t* a, const uint32_t* b) {
    asm volatile(
        "mma.sync.aligned.m16n8k8.row.col.f32.tf32.tf32.f32 "
        "{%0,%1,%2,%3}, {%4,%5,%6,%7}, {%8,%9}, {%0,%1,%2,%3};"
        : "+f"(c[0]), "+f"(c[1]), "+f"(c[2]), "+f"(c[3])
        : "r"(a[0]), "r"(a[1]), "r"(a[2]), "r"(a[3]), "r"(b[0]), "r"(b[1]));
}
__device__ __forceinline__ uint32_t smem_u32(const void* p) {
    uint32_t a;
    asm("{ .reg .u64 t; cvta.to.shared.u64 t, %1; cvt.u32.u64 %0, t; }"
        : "=r"(a) : "l"(p));
    return a;
}
__device__ __forceinline__ void cp16(uint32_t dst, const float* src) {
    asm volatile("cp.async.cg.shared.global [%0], [%1], 16;" :: "r"(dst), "l"(src));
}
__device__ __forceinline__ void cp_commit() { asm volatile("cp.async.commit_group;" ::: "memory"); }
__device__ __forceinline__ void cp_wait0()  { asm volatile("cp.async.wait_group 0;" ::: "memory"); }
__device__ __forceinline__ void cp_wait1()  { asm volatile("cp.async.wait_group 1;" ::: "memory"); }

// ---------------------------------------------------------------------------
// tf32 pre-convert: x -> g_X, {Wq,Wk,Wv,Wo} -> g_W (RNA rounding once).
// ---------------------------------------------------------------------------
__global__ __launch_bounds__(256) void convert_tf32(
    const float* __restrict__ x,
    const float* __restrict__ wq, const float* __restrict__ wk,
    const float* __restrict__ wv, const float* __restrict__ wo)
{
    const size_t idx = (size_t)blockIdx.x * 256 + threadIdx.x;   // float4 index
    const float* src;
    float* dst;
    size_t off;
    if (idx < (1u << 20)) {                       // x: 4M floats = 1M float4
        src = x; dst = g_X; off = idx;
    } else {
        const size_t r = idx - (1u << 20);
        const size_t w = r >> 18;                 // each W: 256K float4
        off = r & ((1u << 18) - 1);
        src = (w == 0) ? wq : (w == 1) ? wk : (w == 2) ? wv : wo;
        dst = g_W + (w << 20);
    }
    float4 v = ((const float4*)src)[off];
    v.x = to_tf32(v.x); v.y = to_tf32(v.y);
    v.z = to_tf32(v.z); v.w = to_tf32(v.w);
    ((float4*)dst)[off] = v;
}

// ---------------------------------------------------------------------------
// tf32 GEMM: C[4096,1024] = A @ W + bias; inputs pre-converted tf32 bits.
// CTA tile 128x128, 256 threads = 2(m) x 4(n) warps; warp tile 64x32.
// 3-stage cp.async pipeline, K-chunk 32 (4 q-steps, 64 MMAs per barrier).
// ---------------------------------------------------------------------------
#define AST 36               // A floats per m-row (144B, 16B aligned)
#define BST 136              // B floats per k-row (544B, 16B aligned)
#define A_F (128 * AST)      // 4608 floats
#define B_F (32 * BST)       // 4352 floats
#define STG_F (A_F + B_F)    // 8960 floats (35840B)
#define NSTG 3
#define OFF_A 128
#define GEMM_SMEM ((OFF_A + NSTG * STG_F) * 4)     // 108032 bytes

__global__ __launch_bounds__(256, 2) void gemm_mma(
    const float* __restrict__ b0, const float* __restrict__ b1,
    const float* __restrict__ b2, float* __restrict__ Cout, int isOut)
{
    extern __shared__ float smem[];

    const int z = blockIdx.z;
    const float* A    = isOut ? g_ATT : g_X;
    const float* W    = isOut ? (g_W + 3u * (1u << 20)) : (g_W + (size_t)z * (1u << 20));
    const float* bias = isOut ? b0 : (z == 0) ? b0 : (z == 1) ? b1 : b2;

    const int tid  = threadIdx.x;
    const int wid  = tid >> 5;
    const int lane = tid & 31;
    const int wm   = wid >> 2;
    const int wn   = wid & 3;
    const int g    = lane >> 2;
    const int tig  = lane & 3;

    const int bm = blockIdx.y * 128;
    const int bn = blockIdx.x * 128;

    if (tid < 128) smem[tid] = bias[bn + tid];

    const uint32_t sb = smem_u32(smem);
    const int arow = tid >> 3, ac4 = tid & 7;        // A f4: row arow+32j, col ac4
    const int brow = tid >> 5, bn4 = tid & 31;       // B f4: krow brow+8j, col bn4

    // issue one K-chunk (32 k) into stage s
    auto issue = [&](int c, int s) {
        const int k0 = c * 32;
        const uint32_t ab = sb + (OFF_A + s * STG_F) * 4;
        const uint32_t bb = ab + A_F * 4;
        #pragma unroll
        for (int j = 0; j < 4; j++) {
            cp16(ab + ((arow + j * 32) * AST + ac4 * 4) * 4,
                 &A[(size_t)(bm + arow + j * 32) * DM + k0 + ac4 * 4]);
            cp16(bb + ((brow + j * 8) * BST + bn4 * 4) * 4,
                 &W[(size_t)(k0 + brow + j * 8) * DM + bn + bn4 * 4]);
        }
        cp_commit();
    };

    issue(0, 0); issue(1, 1);

    float c[4][4][4] = {};

    int stg = 2;                       // next stage to fill
    #pragma unroll 1
    for (int i = 0; i < 32; i++) {
        cp_wait1();
        __syncthreads();
        if (i < 30) {
            issue(i + 2, stg);
            stg = (stg == 2) ? 0 : stg + 1;
        }

        const int cs = (i % 3);
        const float* As = smem + OFF_A + cs * STG_F;
        const float* Bs = As + A_F;
        #pragma unroll
        for (int q = 0; q < 4; q++) {
            uint32_t af[4][4], bf[4][2];
            #pragma unroll
            for (int mf = 0; mf < 4; mf++) {
                const uint32_t* base = (const uint32_t*)&As[(wm * 64 + mf * 16 + g) * AST + q * 8 + tig];
                af[mf][0] = base[0];
                af[mf][1] = base[8 * AST];
                af[mf][2] = base[4];
                af[mf][3] = base[8 * AST + 4];
            }
            #pragma unroll
            for (int nf = 0; nf < 4; nf++) {
                const uint32_t* base = (const uint32_t*)&Bs[(q * 8 + tig) * BST + wn * 32 + nf * 8 + g];
                bf[nf][0] = base[0];
                bf[nf][1] = base[4 * BST];
            }
            #pragma unroll
            for (int mf = 0; mf < 4; mf++)
                #pragma unroll
                for (int nf = 0; nf < 4; nf++)
                    mma_tf32(c[mf][nf], af[mf], bf[nf]);
        }
    }

    // epilogue: bias (+ tf32 convert & Q pre-scale when writing QKV scratch)
    float* O = isOut ? Cout : (z == 0) ? g_Q : (z == 1) ? g_K : g_V;
    const float qsc = (!isOut && z == 0) ? 0.125f : 1.0f;

    #pragma unroll
    for (int mf = 0; mf < 4; mf++) {
        const int row = bm + wm * 64 + mf * 16 + g;
        #pragma unroll
        for (int nf = 0; nf < 4; nf++) {
            const int colt = wn * 32 + nf * 8 + tig * 2;
            const float bx = smem[colt];
            const float by = smem[colt + 1];
            size_t base0, base1;
            if (isOut) {
                base0 = (size_t)row * DM + bn + colt;
                base1 = (size_t)(row + 8) * DM + bn + colt;
            } else {
                const int col = bn + colt;
                const int h = col >> 6, d0 = col & 63;
                const int b_ = row >> 11;
                const int s0 = row & 2047;
                base0 = ((size_t)(b_ * HEADS + h) * SEQ + s0) * DK + d0;
                base1 = base0 + 8 * DK;
            }
            float2 v0 = { c[mf][nf][0] + bx, c[mf][nf][1] + by };
            float2 v1 = { c[mf][nf][2] + bx, c[mf][nf][3] + by };
            if (!isOut) {
                v0.x = to_tf32(v0.x * qsc); v0.y = to_tf32(v0.y * qsc);
                v1.x = to_tf32(v1.x * qsc); v1.y = to_tf32(v1.y * qsc);
            }
            *(float2*)&O[base0] = v0;
            *(float2*)&O[base1] = v1;
        }
    }
}

// ---------------------------------------------------------------------------
// Flash attention on mma.sync tf32 (unchanged from R12-passing version).
// ---------------------------------------------------------------------------
#define KSTR 68
#define VSTR 72
#define PSTR 68
#define KBUF (64 * KSTR)
#define VBUF (64 * VSTR)
#define PBUF (16 * PSTR)
#define FLASH_SMEM ((2 * KBUF + 2 * VBUF + 4 * PBUF) * 4)   // 89088 bytes

__global__ __launch_bounds__(128, 2) void flash_mma()
{
    extern __shared__ float fs[];
    const int tid  = threadIdx.x;
    const int wid  = tid >> 5;
    const int lane = tid & 31;
    const int g    = lane >> 2;
    const int tig  = lane & 3;

    const int bh = blockIdx.y;
    const int qb = blockIdx.x * 64;

    const float* Qg = g_Q + (size_t)bh * SEQ * DK;
    const float* Kg = g_K + (size_t)bh * SEQ * DK;
    const float* Vg = g_V + (size_t)bh * SEQ * DK;

    float* Pw = fs + 2 * KBUF + 2 * VBUF + wid * PBUF;
    const uint32_t sb = smem_u32(fs);

    uint32_t qa[8][4];
    {
        const int r0 = qb + wid * 16 + g;
        #pragma unroll
        for (int ks = 0; ks < 8; ks++) {
            qa[ks][0] = __float_as_uint(Qg[(size_t)r0 * DK + ks * 8 + tig]);
            qa[ks][1] = __float_as_uint(Qg[(size_t)(r0 + 8) * DK + ks * 8 + tig]);
            qa[ks][2] = __float_as_uint(Qg[(size_t)r0 * DK + ks * 8 + tig + 4]);
            qa[ks][3] = __float_as_uint(Qg[(size_t)(r0 + 8) * DK + ks * 8 + tig + 4]);
        }
    }

    float o[8][4] = {};
    float mr0 = -INFINITY, mr1 = -INFINITY;
    float l0 = 0.f, l1 = 0.f;

    auto load_tile = [&](int t) {
        const int buf = t & 1;
        const float* Ksrc = Kg + (size_t)t * 64 * DK;
        const float* Vsrc = Vg + (size_t)t * 64 * DK;
        const uint32_t kd = sb + buf * KBUF * 4;
        const uint32_t vd = sb + (2 * KBUF + buf * VBUF) * 4;
        #pragma unroll
        for (int i = 0; i < 8; i++) {
            int idx = tid + i * 128;
            int row = idx >> 4, c4 = idx & 15;
            cp16(kd + (row * KSTR + c4 * 4) * 4, Ksrc + row * 64 + c4 * 4);
        }
        #pragma unroll
        for (int i = 0; i < 8; i++) {
            int idx = tid + i * 128;
            int row = idx >> 4, c4 = idx & 15;
            cp16(vd + (row * VSTR + c4 * 4) * 4, Vsrc + row * 64 + c4 * 4);
        }
    };

    load_tile(0);
    cp_commit();

    #pragma unroll 1
    for (int t = 0; t < SEQ / 64; t++) {
        cp_wait0();
        __syncthreads();
        if (t + 1 < SEQ / 64) {
            load_tile(t + 1);
            cp_commit();
        }

        const float* Kt = fs + (t & 1) * KBUF;
        const float* Vt = fs + 2 * KBUF + (t & 1) * VBUF;

        float s[8][4] = {};
        #pragma unroll
        for (int ks = 0; ks < 8; ks++) {
            #pragma unroll
            for (int nt = 0; nt < 8; nt++) {
                const uint32_t* bp = (const uint32_t*)&Kt[(nt * 8 + g) * KSTR + ks * 8 + tig];
                uint32_t b[2] = { bp[0], bp[4] };
                mma_tf32(s[nt], qa[ks], b);
            }
        }

        float m0 = -INFINITY, m1 = -INFINITY;
        #pragma unroll
        for (int nt = 0; nt < 8; nt++) {
            m0 = fmaxf(m0, fmaxf(s[nt][0], s[nt][1]));
            m1 = fmaxf(m1, fmaxf(s[nt][2], s[nt][3]));
        }
        m0 = fmaxf(m0, __shfl_xor_sync(0xffffffffu, m0, 1));
        m0 = fmaxf(m0, __shfl_xor_sync(0xffffffffu, m0, 2));
        m1 = fmaxf(m1, __shfl_xor_sync(0xffffffffu, m1, 1));
        m1 = fmaxf(m1, __shfl_xor_sync(0xffffffffu, m1, 2));

        const float nm0 = fmaxf(mr0, m0), nm1 = fmaxf(mr1, m1);
        const float corr0 = exp2a((mr0 - nm0) * LOG2E);
        const float corr1 = exp2a((mr1 - nm1) * LOG2E);
        mr0 = nm0; mr1 = nm1;
        const float c0 = nm0 * LOG2E, c1 = nm1 * LOG2E;

        float t0 = 0.f, t1 = 0.f;
        #pragma unroll
        for (int nt = 0; nt < 8; nt++) {
            float p0 = to_tf32(exp2a(fmaf(s[nt][0], LOG2E, -c0)));
            float p1 = to_tf32(exp2a(fmaf(s[nt][1], LOG2E, -c0)));
            float p2 = to_tf32(exp2a(fmaf(s[nt][2], LOG2E, -c1)));
            float p3 = to_tf32(exp2a(fmaf(s[nt][3], LOG2E, -c1)));
            s[nt][0] = p0; s[nt][1] = p1; s[nt][2] = p2; s[nt][3] = p3;
            t0 += p0 + p1;
            t1 += p2 + p3;
        }
        t0 += __shfl_xor_sync(0xffffffffu, t0, 1);
        t0 += __shfl_xor_sync(0xffffffffu, t0, 2);
        t1 += __shfl_xor_sync(0xffffffffu, t1, 1);
        t1 += __shfl_xor_sync(0xffffffffu, t1, 2);
        l0 = l0 * corr0 + t0;
        l1 = l1 * corr1 + t1;

        #pragma unroll
        for (int nd = 0; nd < 8; nd++) {
            o[nd][0] *= corr0; o[nd][1] *= corr0;
            o[nd][2] *= corr1; o[nd][3] *= corr1;
        }

        #pragma unroll
        for (int nt = 0; nt < 8; nt++) {
            *(float2*)&Pw[g * PSTR + nt * 8 + 2 * tig]       = make_float2(s[nt][0], s[nt][1]);
            *(float2*)&Pw[(g + 8) * PSTR + nt * 8 + 2 * tig] = make_float2(s[nt][2], s[nt][3]);
        }
        __syncwarp();

        #pragma unroll
        for (int ks = 0; ks < 8; ks++) {
            uint32_t a[4];
            a[0] = __float_as_uint(Pw[g * PSTR + ks * 8 + tig]);
            a[1] = __float_as_uint(Pw[(g + 8) * PSTR + ks * 8 + tig]);
            a[2] = __float_as_uint(Pw[g * PSTR + ks * 8 + tig + 4]);
            a[3] = __float_as_uint(Pw[(g + 8) * PSTR + ks * 8 + tig + 4]);
            #pragma unroll
            for (int nd = 0; nd < 8; nd++) {
                const uint32_t* bp0 = (const uint32_t*)&Vt[(ks * 8 + tig) * VSTR + nd * 8 + g];
                const uint32_t* bp1 = (const uint32_t*)&Vt[(ks * 8 + tig + 4) * VSTR + nd * 8 + g];
                uint32_t b[2] = { bp0[0], bp1[0] };
                mma_tf32(o[nd], a, b);
            }
        }
    }

    // epilogue: normalize, tf32-round, store to g_ATT [b,s, h*64+d]
    const float i0 = 1.0f / l0;
    const float i1 = 1.0f / l1;
    const int b_ = bh >> 4;
    const int h  = bh & 15;
    const int s0 = qb + wid * 16 + g;
    float* O0 = &g_ATT[((size_t)b_ * SEQ + s0) * DM + h * DK];
    float* O1 = &g_ATT[((size_t)b_ * SEQ + s0 + 8) * DM + h * DK];
    #pragma unroll
    for (int nd = 0; nd < 8; nd++) {
        *(float2*)&O0[nd * 8 + 2 * tig] =
            make_float2(to_tf32(o[nd][0] * i0), to_tf32(o[nd][1] * i0));
        *(float2*)&O1[nd * 8 + 2 * tig] =
            make_float2(to_tf32(o[nd][2] * i1), to_tf32(o[nd][3] * i1));
    }
}

// ---------------------------------------------------------------------------
extern "C" void kernel_launch(void* const* d_in, const int* in_sizes, int n_in,
                              void* d_out, int out_size)
{
    const float* x  = (const float*)d_in[0];
    const float* Wq = (const float*)d_in[1];
    const float* bq = (const float*)d_in[2];
    const float* Wk = (const float*)d_in[3];
    const float* bk = (const float*)d_in[4];
    const float* Wv = (const float*)d_in[5];
    const float* bv = (const float*)d_in[6];
    const float* Wo = (const float*)d_in[7];
    const float* bo = (const float*)d_in[8];
    float* out = (float*)d_out;

    cudaFuncSetAttribute(gemm_mma, cudaFuncAttributeMaxDynamicSharedMemorySize,
                         GEMM_SMEM);
    cudaFuncSetAttribute(flash_mma, cudaFuncAttributeMaxDynamicSharedMemorySize,
                         FLASH_SMEM);

    // 0) tf32 pre-convert: x -> g_X, W's -> g_W
    convert_tf32<<<8192, 256>>>(x, Wq, Wk, Wv, Wo);

    // 1) QKV projections -> split-head scratch (tf32 bits, Q pre-scaled 1/8)
    dim3 gq(DM / 128, MROWS / 128, 3);
    gemm_mma<<<gq, 256, GEMM_SMEM>>>(bq, bk, bv, nullptr, 0);

    // 2) Flash attention (tensor-core) -> g_ATT (tf32 bits)
    dim3 gf(SEQ / 64, BATCH * HEADS, 1);
    flash_mma<<<gf, 128, FLASH_SMEM>>>();

    // 3) Output projection, reads g_ATT/g_W
    dim3 go(DM / 128, MROWS / 128, 1);
    gemm_mma<<<go, 256, GEMM_SMEM>>>(bo, nullptr, nullptr, out, 1);
}